// round 3
// baseline (speedup 1.0000x reference)
#include <cuda_runtime.h>
#include <math.h>

#define BATCH 20
#define MVIS 262144
#define CDIV(a,b) (((a)+(b)-1)/(b))
#define RBN 0.99950037f   // 1/sqrt(1.001)

// ---------------- static device scratch ----------------
static __device__ float2 g_gridA[BATCH*512*512];
static __device__ float2 g_gridB[BATCH*512*512];
static __device__ float2 g_m0  [BATCH*MVIS];
static __device__ float2 g_m1  [BATCH*MVIS];
static __device__ float2 g_sub0[BATCH*MVIS];
static __device__ float  g_cin [BATCH*2*256*256];
static __device__ float  g_h1  [BATCH*16*256*256];
static __device__ float  g_xc  [BATCH*128*128];

__device__ __forceinline__ float2 cmulf(float2 a, float2 b){
  return make_float2(fmaf(a.x,b.x,-a.y*b.y), fmaf(a.x,b.y,a.y*b.x));
}

// ---------------- FFT: Stockham radix-2 ----------------
template<int N, bool INV>
__global__ void fft_rows(float2* __restrict__ g){
  __shared__ float2 sh[2][N];
  __shared__ float2 tw[N/2];
  const int t = threadIdx.x;                    // N/2 threads
  float2* base = g + ((size_t)blockIdx.y * N + blockIdx.x) * N;
  { float s,c; sincospif(2.0f*t/N,&s,&c); tw[t]=make_float2(c, INV? s:-s); }
  sh[0][t]=base[t]; sh[0][t+N/2]=base[t+N/2];
  __syncthreads();
  int sb=0;
  for (int Ns=1; Ns<N; Ns<<=1){
    float2 v0=sh[sb][t], v1=sh[sb][t+N/2];
    int jm = t & (Ns-1);
    float2 v1w = cmulf(v1, tw[jm*(N/(2*Ns))]);
    int d = ((t-jm)<<1)+jm;
    sh[sb^1][d]    = make_float2(v0.x+v1w.x, v0.y+v1w.y);
    sh[sb^1][d+Ns] = make_float2(v0.x-v1w.x, v0.y-v1w.y);
    sb^=1; __syncthreads();
  }
  const float sc = INV ? 1.0f/N : 1.0f;
  float2 a=sh[sb][t], b2=sh[sb][t+N/2];
  base[t]     = make_float2(a.x*sc, a.y*sc);
  base[t+N/2] = make_float2(b2.x*sc, b2.y*sc);
}

template<int N, bool INV, int TC>
__global__ void fft_cols(float2* __restrict__ g){
  __shared__ float2 sh[2][TC][N+1];
  __shared__ float2 tw[N/2];
  const int t = threadIdx.x;                    // N/2 threads
  float2* base = g + (size_t)blockIdx.y * N * N + blockIdx.x * TC;
  { float s,c; sincospif(2.0f*t/N,&s,&c); tw[t]=make_float2(c, INV? s:-s); }
  for (int i=t; i<N*TC; i+=N/2){
    int r=i/TC, cc=i&(TC-1);
    sh[0][cc][r] = base[(size_t)r*N + cc];
  }
  __syncthreads();
  int sb=0;
  for (int Ns=1; Ns<N; Ns<<=1){
    int jm = t & (Ns-1);
    float2 w = tw[jm*(N/(2*Ns))];
    int d = ((t-jm)<<1)+jm;
    #pragma unroll
    for (int cc=0; cc<TC; cc++){
      float2 v0 = sh[sb][cc][t];
      float2 v1w = cmulf(sh[sb][cc][t+N/2], w);
      sh[sb^1][cc][d]    = make_float2(v0.x+v1w.x, v0.y+v1w.y);
      sh[sb^1][cc][d+Ns] = make_float2(v0.x-v1w.x, v0.y-v1w.y);
    }
    sb^=1; __syncthreads();
  }
  const float sc = INV ? 1.0f/N : 1.0f;
  for (int i=t; i<N*TC; i+=N/2){
    int r=i/TC, cc=i&(TC-1);
    float2 v = sh[sb][cc][r];
    base[(size_t)r*N + cc] = make_float2(v.x*sc, v.y*sc);
  }
}

// ---------------- NUFFT pieces ----------------
__global__ void k_scatter_vis(float2* __restrict__ grid, const float* __restrict__ vr,
                              const float* __restrict__ vi, const float* __restrict__ w,
                              const int* __restrict__ idx){
  int i = blockIdx.x*blockDim.x+threadIdx.x;
  if (i >= BATCH*MVIS) return;
  int b=i/MVIS, k=i-b*MVIS;
  float wv=w[k]; int gi=b*512*512+idx[k];
  atomicAdd(&grid[gi].x, vr[i]*wv);
  atomicAdd(&grid[gi].y, vi[i]*wv);
}

__global__ void k_gather_m0(const float2* __restrict__ grid, const int* __restrict__ idx,
                            const float* __restrict__ w, float2* __restrict__ m0,
                            float2* __restrict__ sub0){
  int i = blockIdx.x*blockDim.x+threadIdx.x;
  if (i >= BATCH*MVIS) return;
  int b=i/MVIS, k=i-b*MVIS;
  float2 v = grid[b*512*512+idx[k]];
  m0[i]=v; float wv=w[k];
  sub0[i]=make_float2(v.x*wv, v.y*wv);
}

__global__ void k_scatter_sel(float2* __restrict__ grid, const float2* __restrict__ src,
                              const int* __restrict__ sel, const int* __restrict__ idx,
                              int n, int srcStride, int gridSize){
  int i = blockIdx.x*blockDim.x+threadIdx.x;
  if (i >= BATCH*n) return;
  int b=i/n, j=i-b*n;
  float2 v = src[(size_t)b*srcStride + sel[j]];
  int gi = b*gridSize + idx[j];
  atomicAdd(&grid[gi].x, v.x);
  atomicAdd(&grid[gi].y, v.y);
}

__global__ void k_gather(const float2* __restrict__ grid, const int* __restrict__ idx,
                         float2* __restrict__ dst, int n, int dstStride, int gridSize){
  int i = blockIdx.x*blockDim.x+threadIdx.x;
  if (i >= BATCH*n) return;
  int b=i/n, j=i-b*n;
  dst[(size_t)b*dstStride + j] = grid[b*gridSize + idx[j]];
}

__global__ void k_set_sel(float2* __restrict__ dstVec, const int* __restrict__ sel,
                          const float2* __restrict__ grid, const int* __restrict__ idx,
                          int n, int dstStride, int gridSize){
  int i = blockIdx.x*blockDim.x+threadIdx.x;
  if (i >= BATCH*n) return;
  int b=i/n, j=i-b*n;
  dstVec[(size_t)b*dstStride + sel[j]] = grid[b*gridSize + idx[j]];
}

__global__ void k_scatterE(float2* __restrict__ gA, float2* __restrict__ gB,
                           const float2* __restrict__ m1, const float2* __restrict__ sub0,
                           const int* __restrict__ sel1, const int* __restrict__ idx1, int n1){
  int i = blockIdx.x*blockDim.x+threadIdx.x;
  if (i >= BATCH*n1) return;
  int b=i/n1, j=i-b*n1;
  float2 v = m1[(size_t)b*n1 + j];
  float2 s = sub0[(size_t)b*MVIS + sel1[j]];
  int gi = b*65536 + idx1[j];
  atomicAdd(&gA[gi].x, v.x);       atomicAdd(&gA[gi].y, v.y);
  atomicAdd(&gB[gi].x, v.x-s.x);   atomicAdd(&gB[gi].y, v.y-s.y);
}

__global__ void k_scatterG(float2* __restrict__ gA, float2* __restrict__ gB,
                           const float2* __restrict__ m0, const float2* __restrict__ sub0,
                           const int* __restrict__ idx0){
  int i = blockIdx.x*blockDim.x+threadIdx.x;
  if (i >= BATCH*MVIS) return;
  int b=i/MVIS, k=i-b*MVIS;
  float2 v=m0[i], s=sub0[i];
  int gi = b*262144 + idx0[k];
  atomicAdd(&gA[gi].x, v.x);       atomicAdd(&gA[gi].y, v.y);
  atomicAdd(&gB[gi].x, v.x-s.x);   atomicAdd(&gB[gi].y, v.y-s.y);
}

template<int S>
__global__ void k_prep_dir(float2* __restrict__ g){
  int i = blockIdx.x*blockDim.x+threadIdx.x;
  if (i >= BATCH*S*S) return;
  int p = i % (S*S);
  int y = p / S, x = p - y*S;
  float2 v = g[i];
  g[i] = (y < S/2 && x < S/2) ? make_float2(v.x,0.f) : make_float2(0.f,0.f);
}

__global__ void k_prep_xc(float2* __restrict__ g, const float* __restrict__ xc){
  int i = blockIdx.x*blockDim.x+threadIdx.x;
  if (i >= BATCH*256*256) return;
  int b=i/65536, p=i-b*65536;
  int y=p/256, x=p-y*256;
  float v = (y<128 && x<128) ? xc[b*16384 + y*128 + x] : 0.f;
  g[i] = make_float2(v, 0.f);
}

template<int S, int NO>
__global__ void k_extract(const float2* __restrict__ gA, const float2* __restrict__ gB,
                          float* __restrict__ cin){
  int i = blockIdx.x*blockDim.x+threadIdx.x;
  if (i >= BATCH*NO*NO) return;
  int b=i/(NO*NO), p=i-b*NO*NO;
  int y=p/NO, x=p-y*NO;
  size_t gi = (size_t)b*S*S + (size_t)y*S + x;
  cin[(size_t)(b*2+0)*NO*NO + p] = gA[gi].x;
  cin[(size_t)(b*2+1)*NO*NO + p] = gB[gi].x;
}

// ---------------- conv block ----------------
template<int F, int H>
__global__ void __launch_bounds__(256) conv1_k(
    const float* __restrict__ cin, const float* __restrict__ W1,
    const float* __restrict__ b1, const float* __restrict__ g1,
    const float* __restrict__ be1, float* __restrict__ h1){
  __shared__ float si[2][18][18];
  __shared__ float sw[18*F];
  __shared__ float sb[F], sg[F], sbe[F];
  const int tx=threadIdx.x, ty=threadIdx.y, tid=ty*16+tx;
  const int b=blockIdx.z, x0=blockIdx.x*16, y0=blockIdx.y*16;
  for (int i=tid; i<18*F; i+=256) sw[i]=W1[i];
  for (int i=tid; i<F; i+=256){ sb[i]=b1[i]; sg[i]=g1[i]*RBN; sbe[i]=be1[i]; }
  const float* cb = cin + (size_t)b*2*H*H;
  for (int c=0;c<2;c++)
    for (int i=tid;i<18*18;i+=256){
      int yy=i/18, xx=i-yy*18;
      int gy=y0+yy-1, gx=x0+xx-1;
      si[c][yy][xx] = (gy>=0&&gy<H&&gx>=0&&gx<H) ? cb[c*H*H + gy*H + gx] : 0.f;
    }
  __syncthreads();
  float acc[F];
  #pragma unroll
  for (int o=0;o<F;o++) acc[o]=sb[o];
  #pragma unroll
  for (int ky=0;ky<3;ky++)
    #pragma unroll
    for (int kx=0;kx<3;kx++)
      #pragma unroll
      for (int c=0;c<2;c++){
        float v = si[c][ty+ky][tx+kx];
        const float* wt = sw + ((ky*3+kx)*2+c)*F;
        #pragma unroll
        for (int o=0;o<F;o++) acc[o]=fmaf(v, wt[o], acc[o]);
      }
  const int y=y0+ty, x=x0+tx;
  float* hb = h1 + (size_t)b*F*H*H + (size_t)y*H + x;
  #pragma unroll
  for (int o=0;o<F;o++)
    hb[(size_t)o*H*H] = fmaf(fmaxf(acc[o],0.f), sg[o], sbe[o]);
}

// conv2 (3x3 F->F, relu, bn) fused with conv3 (1x1 F->1) + sigmoid
template<int F, int H>
__global__ void __launch_bounds__(256) conv23_k(
    const float* __restrict__ h1, const float* __restrict__ W2,
    const float* __restrict__ b2, const float* __restrict__ g2,
    const float* __restrict__ be2, const float* __restrict__ W3,
    const float* __restrict__ b3, float* __restrict__ out){
  __shared__ float sw[9*F*F];
  __shared__ float tile[18][18];
  __shared__ float sb[F], sg[F], sbe[F], sw3[F];
  const int tx=threadIdx.x, ty=threadIdx.y, tid=ty*16+tx;
  const int b=blockIdx.z, x0=blockIdx.x*16, y0=blockIdx.y*16;
  for (int i=tid; i<9*F*F; i+=256){
    int oc=i%F, r=i/F, tap=r%9, ic=r/9;
    sw[i] = W2[(tap*F+ic)*F+oc];
  }
  for (int i=tid; i<F; i+=256){ sb[i]=b2[i]; sg[i]=g2[i]*RBN; sbe[i]=be2[i]; sw3[i]=W3[i]; }
  __syncthreads();
  float acc[F];
  #pragma unroll
  for (int o=0;o<F;o++) acc[o]=sb[o];
  const float* hb = h1 + (size_t)b*F*H*H;
  for (int ic=0; ic<F; ic++){
    __syncthreads();
    for (int i=tid;i<18*18;i+=256){
      int yy=i/18, xx=i-yy*18;
      int gy=y0+yy-1, gx=x0+xx-1;
      tile[yy][xx] = (gy>=0&&gy<H&&gx>=0&&gx<H) ? hb[(size_t)ic*H*H + gy*H + gx] : 0.f;
    }
    __syncthreads();
    const float* wi = sw + ic*9*F;
    #pragma unroll
    for (int ky=0;ky<3;ky++)
      #pragma unroll
      for (int kx=0;kx<3;kx++){
        float v = tile[ty+ky][tx+kx];
        const float* wt = wi + (ky*3+kx)*F;
        #pragma unroll
        for (int o=0;o<F;o++) acc[o]=fmaf(v, wt[o], acc[o]);
      }
  }
  float s = b3[0];
  #pragma unroll
  for (int o=0;o<F;o++)
    s = fmaf(fmaf(fmaxf(acc[o],0.f), sg[o], sbe[o]), sw3[o], s);
  out[(size_t)b*H*H + (size_t)(y0+ty)*H + (x0+tx)] = 1.f/(1.f+__expf(-s));
}

// ---------------- launch ----------------
extern "C" void kernel_launch(void* const* d_in, const int* in_sizes, int n_in,
                              void* d_out, int out_size){
  const float* vr = (const float*)d_in[0];
  const float* vi = (const float*)d_in[1];
  const float* w  = (const float*)d_in[2];
  const float *c0w1=(const float*)d_in[3],  *c0b1=(const float*)d_in[4],
              *c0g1=(const float*)d_in[5],  *c0be1=(const float*)d_in[6],
              *c0w2=(const float*)d_in[7],  *c0b2=(const float*)d_in[8],
              *c0g2=(const float*)d_in[9],  *c0be2=(const float*)d_in[10],
              *c0w3=(const float*)d_in[11], *c0b3=(const float*)d_in[12];
  const float *c1w1=(const float*)d_in[13], *c1b1=(const float*)d_in[14],
              *c1g1=(const float*)d_in[15], *c1be1=(const float*)d_in[16],
              *c1w2=(const float*)d_in[17], *c1b2=(const float*)d_in[18],
              *c1g2=(const float*)d_in[19], *c1be2=(const float*)d_in[20],
              *c1w3=(const float*)d_in[21], *c1b3=(const float*)d_in[22];
  const int* idx0=(const int*)d_in[23];
  const int* idx1=(const int*)d_in[24];
  const int* idx2=(const int*)d_in[25];
  const int* sel1=(const int*)d_in[26];
  const int* sel2=(const int*)d_in[27];
  const int n1 = in_sizes[24], n2 = in_sizes[25];
  float* out = (float*)d_out;

  float2 *gA,*gB,*m0,*m1,*sub0; float *cin,*h1,*xc;
  cudaGetSymbolAddress((void**)&gA,   g_gridA);
  cudaGetSymbolAddress((void**)&gB,   g_gridB);
  cudaGetSymbolAddress((void**)&m0,   g_m0);
  cudaGetSymbolAddress((void**)&m1,   g_m1);
  cudaGetSymbolAddress((void**)&sub0, g_sub0);
  cudaGetSymbolAddress((void**)&cin,  g_cin);
  cudaGetSymbolAddress((void**)&h1,   g_h1);
  cudaGetSymbolAddress((void**)&xc,   g_xc);

  const int TPB=256;
  // A: adj0 of vis*w
  cudaMemsetAsync(gA, 0, (size_t)BATCH*262144*sizeof(float2), 0);
  k_scatter_vis<<<CDIV(BATCH*MVIS,TPB),TPB>>>(gA, vr, vi, w, idx0);
  fft_rows<512,true ><<<dim3(512,BATCH),256>>>(gA);
  fft_cols<512,true ,4><<<dim3(128,BATCH),256>>>(gA);
  // B: dir0 -> m0, sub0
  k_prep_dir<512><<<CDIV(BATCH*262144,TPB),TPB>>>(gA);
  fft_rows<512,false><<<dim3(512,BATCH),256>>>(gA);
  fft_cols<512,false,4><<<dim3(128,BATCH),256>>>(gA);
  k_gather_m0<<<CDIV(BATCH*MVIS,TPB),TPB>>>(gA, idx0, w, m0, sub0);
  // C: adj1 of m0[sel1]
  cudaMemsetAsync(gB, 0, (size_t)BATCH*65536*sizeof(float2), 0);
  k_scatter_sel<<<CDIV(BATCH*n1,TPB),TPB>>>(gB, m0, sel1, idx1, n1, MVIS, 65536);
  fft_rows<256,true ><<<dim3(256,BATCH),128>>>(gB);
  fft_cols<256,true ,8><<<dim3(32,BATCH),128>>>(gB);
  // D: dir1 -> m1
  k_prep_dir<256><<<CDIV(BATCH*65536,TPB),TPB>>>(gB);
  fft_rows<256,false><<<dim3(256,BATCH),128>>>(gB);
  fft_cols<256,false,8><<<dim3(32,BATCH),128>>>(gB);
  k_gather<<<CDIV(BATCH*n1,TPB),TPB>>>(gB, idx1, m1, n1, n1, 65536);
  // E: adj2 of m1[sel2]
  cudaMemsetAsync(gA, 0, (size_t)BATCH*16384*sizeof(float2), 0);
  k_scatter_sel<<<CDIV(BATCH*n2,TPB),TPB>>>(gA, m1, sel2, idx2, n2, n1, 16384);
  fft_rows<128,true ><<<dim3(128,BATCH),64>>>(gA);
  fft_cols<128,true ,8><<<dim3(16,BATCH),64>>>(gA);
  // F: dir2 -> meas; m1 becomes full1
  k_prep_dir<128><<<CDIV(BATCH*16384,TPB),TPB>>>(gA);
  fft_rows<128,false><<<dim3(128,BATCH),64>>>(gA);
  fft_cols<128,false,8><<<dim3(16,BATCH),64>>>(gA);
  k_set_sel<<<CDIV(BATCH*n2,TPB),TPB>>>(m1, sel2, gA, idx2, n2, n1, 16384);
  // G: two adj1 (full1, full1 - sub1)
  cudaMemsetAsync(gA, 0, (size_t)BATCH*65536*sizeof(float2), 0);
  cudaMemsetAsync(gB, 0, (size_t)BATCH*65536*sizeof(float2), 0);
  k_scatterE<<<CDIV(BATCH*n1,TPB),TPB>>>(gA, gB, m1, sub0, sel1, idx1, n1);
  fft_rows<256,true ><<<dim3(256,BATCH),128>>>(gA);
  fft_cols<256,true ,8><<<dim3(32,BATCH),128>>>(gA);
  fft_rows<256,true ><<<dim3(256,BATCH),128>>>(gB);
  fft_cols<256,true ,8><<<dim3(32,BATCH),128>>>(gB);
  k_extract<256,128><<<CDIV(BATCH*16384,TPB),TPB>>>(gA, gB, cin);
  // H: conv block p0 (F=32 @128) -> xc
  conv1_k <32,128><<<dim3(8,8,BATCH),dim3(16,16)>>>(cin, c0w1, c0b1, c0g1, c0be1, h1);
  conv23_k<32,128><<<dim3(8,8,BATCH),dim3(16,16)>>>(h1, c0w2, c0b2, c0g2, c0be2, c0w3, c0b3, xc);
  // I: dir1 of xc; m0 becomes full0
  k_prep_xc<<<CDIV(BATCH*65536,TPB),TPB>>>(gA, xc);
  fft_rows<256,false><<<dim3(256,BATCH),128>>>(gA);
  fft_cols<256,false,8><<<dim3(32,BATCH),128>>>(gA);
  k_set_sel<<<CDIV(BATCH*n1,TPB),TPB>>>(m0, sel1, gA, idx1, n1, MVIS, 65536);
  // J: two adj0 (full0, full0 - sub0)
  cudaMemsetAsync(gA, 0, (size_t)BATCH*262144*sizeof(float2), 0);
  cudaMemsetAsync(gB, 0, (size_t)BATCH*262144*sizeof(float2), 0);
  k_scatterG<<<CDIV(BATCH*MVIS,TPB),TPB>>>(gA, gB, m0, sub0, idx0);
  fft_rows<512,true ><<<dim3(512,BATCH),256>>>(gA);
  fft_cols<512,true ,4><<<dim3(128,BATCH),256>>>(gA);
  fft_rows<512,true ><<<dim3(512,BATCH),256>>>(gB);
  fft_cols<512,true ,4><<<dim3(128,BATCH),256>>>(gB);
  k_extract<512,256><<<CDIV(BATCH*65536,TPB),TPB>>>(gA, gB, cin);
  // K: conv block p1 (F=16 @256) -> out
  conv1_k <16,256><<<dim3(16,16,BATCH),dim3(16,16)>>>(cin, c1w1, c1b1, c1g1, c1be1, h1);
  conv23_k<16,256><<<dim3(16,16,BATCH),dim3(16,16)>>>(h1, c1w2, c1b2, c1g2, c1be2, c1w3, c1b3, out);
}

// round 5
// speedup vs baseline: 1.1759x; 1.1759x over previous
#include <cuda_runtime.h>
#include <math.h>

#define BATCH 20
#define MVIS 262144
#define CDIV(a,b) (((a)+(b)-1)/(b))
#define RBN 0.99950037f   // 1/sqrt(1.001)

// ---------------- static device scratch ----------------
static __device__ float2 g_gridA[BATCH*512*512];
static __device__ float2 g_gridB[BATCH*512*512];
static __device__ float2 g_m0  [BATCH*MVIS];
static __device__ float2 g_m1  [BATCH*MVIS];
static __device__ float2 g_sub0[BATCH*MVIS];
static __device__ float  g_cin [BATCH*2*256*256];
static __device__ float  g_h1  [BATCH*16*256*256];
static __device__ float  g_xc  [BATCH*128*128];

__device__ __forceinline__ float2 cmulf(float2 a, float2 b){
  return make_float2(fmaf(a.x,b.x,-a.y*b.y), fmaf(a.x,b.y,a.y*b.x));
}
__device__ __forceinline__ constexpr int IX(int i){ return i + (i>>4); }

// ---- packed f32x2 helpers ----
__device__ __forceinline__ unsigned long long pack2(float lo, float hi){
  unsigned long long r;
  asm("mov.b64 %0, {%1, %2};" : "=l"(r) : "r"(__float_as_uint(lo)), "r"(__float_as_uint(hi)));
  return r;
}
__device__ __forceinline__ unsigned long long dup2(float v){
  unsigned long long r;
  asm("mov.b64 %0, {%1, %1};" : "=l"(r) : "r"(__float_as_uint(v)));
  return r;
}
__device__ __forceinline__ void fma2(unsigned long long &d, unsigned long long a,
                                     unsigned long long b, unsigned long long c){
  asm("fma.rn.f32x2 %0, %1, %2, %3;" : "=l"(d) : "l"(a), "l"(b), "l"(c));
}
__device__ __forceinline__ float2 unpack2(unsigned long long v){
  unsigned lo, hi;
  asm("mov.b64 {%0, %1}, %2;" : "=r"(lo), "=r"(hi) : "l"(v));
  return make_float2(__uint_as_float(lo), __uint_as_float(hi));
}

// ---------------- FFT: Stockham radix-4 (+radix-2 tail) ----------------
template<int N, bool INV>
__global__ void fft4_rows(float2* __restrict__ g){
  constexpr int L  = (N==512)?9:(N==256)?8:7;
  constexpr int S4 = L/2;
  constexpr bool ODD = (L & 1);
  __shared__ float2 sh[2][N + N/16];
  const int t = threadIdx.x;                    // N/4 threads
  float2* base = g + ((size_t)blockIdx.y * N + blockIdx.x) * N;
  #pragma unroll
  for (int k=0;k<4;k++) sh[0][IX(t + k*(N/4))] = base[t + k*(N/4)];
  __syncthreads();
  int sb=0;
  #pragma unroll
  for (int s=0; s<S4; s++){
    const int Ns = 1 << (2*s);
    const int jm = t & (Ns-1);
    float2 v0=sh[sb][IX(t)],       v1=sh[sb][IX(t+N/4)];
    float2 v2=sh[sb][IX(t+N/2)],   v3=sh[sb][IX(t+3*(N/4))];
    float sn,cs; sincospif(((INV?2.0f:-2.0f)*jm)/(4*Ns), &sn, &cs);
    float2 w1=make_float2(cs,sn);
    float2 w2=cmulf(w1,w1), w3=cmulf(w2,w1);
    float2 a1=cmulf(v1,w1), a2=cmulf(v2,w2), a3=cmulf(v3,w3);
    float2 t0=make_float2(v0.x+a2.x, v0.y+a2.y);
    float2 t1=make_float2(v0.x-a2.x, v0.y-a2.y);
    float2 t2=make_float2(a1.x+a3.x, a1.y+a3.y);
    float2 t3=make_float2(a1.x-a3.x, a1.y-a3.y);
    float2 j3 = INV ? make_float2(-t3.y, t3.x) : make_float2(t3.y, -t3.x);
    int d = ((t - jm) << 2) + jm;
    sh[sb^1][IX(d)]      = make_float2(t0.x+t2.x, t0.y+t2.y);
    sh[sb^1][IX(d+Ns)]   = make_float2(t1.x+j3.x, t1.y+j3.y);
    sh[sb^1][IX(d+2*Ns)] = make_float2(t0.x-t2.x, t0.y-t2.y);
    sh[sb^1][IX(d+3*Ns)] = make_float2(t1.x-j3.x, t1.y-j3.y);
    sb^=1; __syncthreads();
  }
  if (ODD){
    #pragma unroll
    for (int q=0;q<2;q++){
      int j = t + q*(N/4);
      float2 v0 = sh[sb][IX(j)], v1 = sh[sb][IX(j+N/2)];
      float sn,cs; sincospif(((INV?2.0f:-2.0f)*j)/N, &sn, &cs);
      float2 vw = cmulf(v1, make_float2(cs,sn));
      sh[sb^1][IX(j)]     = make_float2(v0.x+vw.x, v0.y+vw.y);
      sh[sb^1][IX(j+N/2)] = make_float2(v0.x-vw.x, v0.y-vw.y);
    }
    sb^=1; __syncthreads();
  }
  const float sc = INV ? 1.0f/N : 1.0f;
  #pragma unroll
  for (int k=0;k<4;k++){
    float2 v = sh[sb][IX(t + k*(N/4))];
    base[t + k*(N/4)] = make_float2(v.x*sc, v.y*sc);
  }
}

template<int N, bool INV, int TC>
__global__ void fft4_cols(float2* __restrict__ g){
  constexpr int L  = (N==512)?9:(N==256)?8:7;
  constexpr int S4 = L/2;
  constexpr bool ODD = (L & 1);
  __shared__ float2 sh[2][TC][N + N/16];
  const int t = threadIdx.x;                    // N/4 threads
  float2* base = g + (size_t)blockIdx.y * N * N + blockIdx.x * TC;
  for (int i=t; i<N*TC; i+=N/4){
    int r=i/TC, cc=i&(TC-1);
    sh[0][cc][IX(r)] = base[(size_t)r*N + cc];
  }
  __syncthreads();
  int sb=0;
  #pragma unroll
  for (int s=0; s<S4; s++){
    const int Ns = 1 << (2*s);
    const int jm = t & (Ns-1);
    float sn,cs; sincospif(((INV?2.0f:-2.0f)*jm)/(4*Ns), &sn, &cs);
    float2 w1=make_float2(cs,sn);
    float2 w2=cmulf(w1,w1), w3=cmulf(w2,w1);
    const int d = ((t - jm) << 2) + jm;
    #pragma unroll
    for (int cc=0; cc<TC; cc++){
      float2 v0=sh[sb][cc][IX(t)],     v1=sh[sb][cc][IX(t+N/4)];
      float2 v2=sh[sb][cc][IX(t+N/2)], v3=sh[sb][cc][IX(t+3*(N/4))];
      float2 a1=cmulf(v1,w1), a2=cmulf(v2,w2), a3=cmulf(v3,w3);
      float2 t0=make_float2(v0.x+a2.x, v0.y+a2.y);
      float2 t1=make_float2(v0.x-a2.x, v0.y-a2.y);
      float2 t2=make_float2(a1.x+a3.x, a1.y+a3.y);
      float2 t3=make_float2(a1.x-a3.x, a1.y-a3.y);
      float2 j3 = INV ? make_float2(-t3.y, t3.x) : make_float2(t3.y, -t3.x);
      sh[sb^1][cc][IX(d)]      = make_float2(t0.x+t2.x, t0.y+t2.y);
      sh[sb^1][cc][IX(d+Ns)]   = make_float2(t1.x+j3.x, t1.y+j3.y);
      sh[sb^1][cc][IX(d+2*Ns)] = make_float2(t0.x-t2.x, t0.y-t2.y);
      sh[sb^1][cc][IX(d+3*Ns)] = make_float2(t1.x-j3.x, t1.y-j3.y);
    }
    sb^=1; __syncthreads();
  }
  if (ODD){
    #pragma unroll
    for (int q=0;q<2;q++){
      int j = t + q*(N/4);
      float sn,cs; sincospif(((INV?2.0f:-2.0f)*j)/N, &sn, &cs);
      float2 w = make_float2(cs,sn);
      #pragma unroll
      for (int cc=0; cc<TC; cc++){
        float2 v0 = sh[sb][cc][IX(j)], v1 = sh[sb][cc][IX(j+N/2)];
        float2 vw = cmulf(v1, w);
        sh[sb^1][cc][IX(j)]     = make_float2(v0.x+vw.x, v0.y+vw.y);
        sh[sb^1][cc][IX(j+N/2)] = make_float2(v0.x-vw.x, v0.y-vw.y);
      }
    }
    sb^=1; __syncthreads();
  }
  const float sc = INV ? 1.0f/N : 1.0f;
  for (int i=t; i<N*TC; i+=N/4){
    int r=i/TC, cc=i&(TC-1);
    float2 v = sh[sb][cc][IX(r)];
    base[(size_t)r*N + cc] = make_float2(v.x*sc, v.y*sc);
  }
}

// ---------------- NUFFT pieces ----------------
__global__ void k_scatter_vis(float2* __restrict__ grid, const float* __restrict__ vr,
                              const float* __restrict__ vi, const float* __restrict__ w,
                              const int* __restrict__ idx){
  int i = blockIdx.x*blockDim.x+threadIdx.x;
  if (i >= BATCH*MVIS) return;
  int b=i/MVIS, k=i-b*MVIS;
  float wv=w[k]; int gi=b*512*512+idx[k];
  atomicAdd(&grid[gi].x, vr[i]*wv);
  atomicAdd(&grid[gi].y, vi[i]*wv);
}

__global__ void k_gather_m0(const float2* __restrict__ grid, const int* __restrict__ idx,
                            const float* __restrict__ w, float2* __restrict__ m0,
                            float2* __restrict__ sub0){
  int i = blockIdx.x*blockDim.x+threadIdx.x;
  if (i >= BATCH*MVIS) return;
  int b=i/MVIS, k=i-b*MVIS;
  float2 v = grid[b*512*512+idx[k]];
  m0[i]=v; float wv=w[k];
  sub0[i]=make_float2(v.x*wv, v.y*wv);
}

__global__ void k_scatter_sel(float2* __restrict__ grid, const float2* __restrict__ src,
                              const int* __restrict__ sel, const int* __restrict__ idx,
                              int n, int srcStride, int gridSize){
  int i = blockIdx.x*blockDim.x+threadIdx.x;
  if (i >= BATCH*n) return;
  int b=i/n, j=i-b*n;
  float2 v = src[(size_t)b*srcStride + sel[j]];
  int gi = b*gridSize + idx[j];
  atomicAdd(&grid[gi].x, v.x);
  atomicAdd(&grid[gi].y, v.y);
}

__global__ void k_gather(const float2* __restrict__ grid, const int* __restrict__ idx,
                         float2* __restrict__ dst, int n, int dstStride, int gridSize){
  int i = blockIdx.x*blockDim.x+threadIdx.x;
  if (i >= BATCH*n) return;
  int b=i/n, j=i-b*n;
  dst[(size_t)b*dstStride + j] = grid[b*gridSize + idx[j]];
}

__global__ void k_set_sel(float2* __restrict__ dstVec, const int* __restrict__ sel,
                          const float2* __restrict__ grid, const int* __restrict__ idx,
                          int n, int dstStride, int gridSize){
  int i = blockIdx.x*blockDim.x+threadIdx.x;
  if (i >= BATCH*n) return;
  int b=i/n, j=i-b*n;
  dstVec[(size_t)b*dstStride + sel[j]] = grid[b*gridSize + idx[j]];
}

__global__ void k_scatterE(float2* __restrict__ gA, float2* __restrict__ gB,
                           const float2* __restrict__ m1, const float2* __restrict__ sub0,
                           const int* __restrict__ sel1, const int* __restrict__ idx1, int n1){
  int i = blockIdx.x*blockDim.x+threadIdx.x;
  if (i >= BATCH*n1) return;
  int b=i/n1, j=i-b*n1;
  float2 v = m1[(size_t)b*n1 + j];
  float2 s = sub0[(size_t)b*MVIS + sel1[j]];
  int gi = b*65536 + idx1[j];
  atomicAdd(&gA[gi].x, v.x);       atomicAdd(&gA[gi].y, v.y);
  atomicAdd(&gB[gi].x, v.x-s.x);   atomicAdd(&gB[gi].y, v.y-s.y);
}

__global__ void k_scatterG(float2* __restrict__ gA, float2* __restrict__ gB,
                           const float2* __restrict__ m0, const float2* __restrict__ sub0,
                           const int* __restrict__ idx0){
  int i = blockIdx.x*blockDim.x+threadIdx.x;
  if (i >= BATCH*MVIS) return;
  int b=i/MVIS, k=i-b*MVIS;
  float2 v=m0[i], s=sub0[i];
  int gi = b*262144 + idx0[k];
  atomicAdd(&gA[gi].x, v.x);       atomicAdd(&gA[gi].y, v.y);
  atomicAdd(&gB[gi].x, v.x-s.x);   atomicAdd(&gB[gi].y, v.y-s.y);
}

template<int S>
__global__ void k_prep_dir(float2* __restrict__ g){
  int i = blockIdx.x*blockDim.x+threadIdx.x;
  if (i >= BATCH*S*S) return;
  int p = i % (S*S);
  int y = p / S, x = p - y*S;
  float2 v = g[i];
  g[i] = (y < S/2 && x < S/2) ? make_float2(v.x,0.f) : make_float2(0.f,0.f);
}

__global__ void k_prep_xc(float2* __restrict__ g, const float* __restrict__ xc){
  int i = blockIdx.x*blockDim.x+threadIdx.x;
  if (i >= BATCH*256*256) return;
  int b=i/65536, p=i-b*65536;
  int y=p/256, x=p-y*256;
  float v = (y<128 && x<128) ? xc[b*16384 + y*128 + x] : 0.f;
  g[i] = make_float2(v, 0.f);
}

template<int S, int NO>
__global__ void k_extract(const float2* __restrict__ gA, const float2* __restrict__ gB,
                          float* __restrict__ cin){
  int i = blockIdx.x*blockDim.x+threadIdx.x;
  if (i >= BATCH*NO*NO) return;
  int b=i/(NO*NO), p=i-b*NO*NO;
  int y=p/NO, x=p-y*NO;
  size_t gi = (size_t)b*S*S + (size_t)y*S + x;
  cin[(size_t)(b*2+0)*NO*NO + p] = gA[gi].x;
  cin[(size_t)(b*2+1)*NO*NO + p] = gB[gi].x;
}

// ---------------- conv block (packed f32x2) ----------------
template<int F, int H>
__global__ void __launch_bounds__(256) conv1_k(
    const float* __restrict__ cin, const float* __restrict__ W1,
    const float* __restrict__ b1, const float* __restrict__ g1,
    const float* __restrict__ be1, float* __restrict__ h1){
  __shared__ float si[2][18][18];
  __shared__ float sw[18*F];
  __shared__ float sb[F], sg[F], sbe[F];
  const int tx=threadIdx.x, ty=threadIdx.y, tid=ty*16+tx;
  const int b=blockIdx.z, x0=blockIdx.x*16, y0=blockIdx.y*16;
  for (int i=tid; i<18*F; i+=256) sw[i]=W1[i];
  for (int i=tid; i<F; i+=256){ sb[i]=b1[i]; sg[i]=g1[i]*RBN; sbe[i]=be1[i]; }
  const float* cb = cin + (size_t)b*2*H*H;
  for (int c=0;c<2;c++)
    for (int i=tid;i<18*18;i+=256){
      int yy=i/18, xx=i-yy*18;
      int gy=y0+yy-1, gx=x0+xx-1;
      si[c][yy][xx] = (gy>=0&&gy<H&&gx>=0&&gx<H) ? cb[c*H*H + gy*H + gx] : 0.f;
    }
  __syncthreads();
  unsigned long long acc2[F/2];
  #pragma unroll
  for (int o2=0;o2<F/2;o2++) acc2[o2]=pack2(sb[2*o2], sb[2*o2+1]);
  #pragma unroll
  for (int ky=0;ky<3;ky++)
    #pragma unroll
    for (int kx=0;kx<3;kx++)
      #pragma unroll
      for (int c=0;c<2;c++){
        unsigned long long vv = dup2(si[c][ty+ky][tx+kx]);
        const float* wt = sw + ((ky*3+kx)*2+c)*F;
        #pragma unroll
        for (int o2=0;o2<F/2;o2++)
          fma2(acc2[o2], vv, *reinterpret_cast<const unsigned long long*>(wt + 2*o2), acc2[o2]);
      }
  const int y=y0+ty, x=x0+tx;
  float* hb = h1 + (size_t)b*F*H*H + (size_t)y*H + x;
  #pragma unroll
  for (int o2=0;o2<F/2;o2++){
    float2 a = unpack2(acc2[o2]);
    hb[(size_t)(2*o2  )*H*H] = fmaf(fmaxf(a.x,0.f), sg[2*o2  ], sbe[2*o2  ]);
    hb[(size_t)(2*o2+1)*H*H] = fmaf(fmaxf(a.y,0.f), sg[2*o2+1], sbe[2*o2+1]);
  }
}

// conv2 (3x3 F->F, relu, bn) fused with conv3 (1x1 F->1) + sigmoid
template<int F, int H>
__global__ void __launch_bounds__(256) conv23_k(
    const float* __restrict__ h1, const float* __restrict__ W2,
    const float* __restrict__ b2, const float* __restrict__ g2,
    const float* __restrict__ be2, const float* __restrict__ W3,
    const float* __restrict__ b3, float* __restrict__ out){
  __shared__ float sw[9*F*F];
  __shared__ float tile[18][18];
  __shared__ float sb[F], sg[F], sbe[F], sw3[F];
  const int tx=threadIdx.x, ty=threadIdx.y, tid=ty*16+tx;
  const int b=blockIdx.z, x0=blockIdx.x*16, y0=blockIdx.y*16;
  for (int i=tid; i<9*F*F; i+=256){
    int oc=i%F, r=i/F, tap=r%9, ic=r/9;
    sw[i] = W2[(tap*F+ic)*F+oc];
  }
  for (int i=tid; i<F; i+=256){ sb[i]=b2[i]; sg[i]=g2[i]*RBN; sbe[i]=be2[i]; sw3[i]=W3[i]; }
  __syncthreads();
  unsigned long long acc2[F/2];
  #pragma unroll
  for (int o2=0;o2<F/2;o2++) acc2[o2]=pack2(sb[2*o2], sb[2*o2+1]);
  const float* hb = h1 + (size_t)b*F*H*H;
  for (int ic=0; ic<F; ic++){
    __syncthreads();
    for (int i=tid;i<18*18;i+=256){
      int yy=i/18, xx=i-yy*18;
      int gy=y0+yy-1, gx=x0+xx-1;
      tile[yy][xx] = (gy>=0&&gy<H&&gx>=0&&gx<H) ? hb[(size_t)ic*H*H + gy*H + gx] : 0.f;
    }
    __syncthreads();
    const float* wi = sw + ic*9*F;
    #pragma unroll
    for (int ky=0;ky<3;ky++)
      #pragma unroll
      for (int kx=0;kx<3;kx++){
        unsigned long long vv = dup2(tile[ty+ky][tx+kx]);
        const float* wt = wi + (ky*3+kx)*F;
        #pragma unroll
        for (int o2=0;o2<F/2;o2++)
          fma2(acc2[o2], vv, *reinterpret_cast<const unsigned long long*>(wt + 2*o2), acc2[o2]);
      }
  }
  float s = b3[0];
  #pragma unroll
  for (int o2=0;o2<F/2;o2++){
    float2 a = unpack2(acc2[o2]);
    s = fmaf(fmaf(fmaxf(a.x,0.f), sg[2*o2  ], sbe[2*o2  ]), sw3[2*o2  ], s);
    s = fmaf(fmaf(fmaxf(a.y,0.f), sg[2*o2+1], sbe[2*o2+1]), sw3[2*o2+1], s);
  }
  out[(size_t)b*H*H + (size_t)(y0+ty)*H + (x0+tx)] = 1.f/(1.f+__expf(-s));
}

// ---------------- launch ----------------
extern "C" void kernel_launch(void* const* d_in, const int* in_sizes, int n_in,
                              void* d_out, int out_size){
  const float* vr = (const float*)d_in[0];
  const float* vi = (const float*)d_in[1];
  const float* w  = (const float*)d_in[2];
  const float *c0w1=(const float*)d_in[3],  *c0b1=(const float*)d_in[4],
              *c0g1=(const float*)d_in[5],  *c0be1=(const float*)d_in[6],
              *c0w2=(const float*)d_in[7],  *c0b2=(const float*)d_in[8],
              *c0g2=(const float*)d_in[9],  *c0be2=(const float*)d_in[10],
              *c0w3=(const float*)d_in[11], *c0b3=(const float*)d_in[12];
  const float *c1w1=(const float*)d_in[13], *c1b1=(const float*)d_in[14],
              *c1g1=(const float*)d_in[15], *c1be1=(const float*)d_in[16],
              *c1w2=(const float*)d_in[17], *c1b2=(const float*)d_in[18],
              *c1g2=(const float*)d_in[19], *c1be2=(const float*)d_in[20],
              *c1w3=(const float*)d_in[21], *c1b3=(const float*)d_in[22];
  const int* idx0=(const int*)d_in[23];
  const int* idx1=(const int*)d_in[24];
  const int* idx2=(const int*)d_in[25];
  const int* sel1=(const int*)d_in[26];
  const int* sel2=(const int*)d_in[27];
  const int n1 = in_sizes[24], n2 = in_sizes[25];
  float* out = (float*)d_out;

  float2 *gA,*gB,*m0,*m1,*sub0; float *cin,*h1,*xc;
  cudaGetSymbolAddress((void**)&gA,   g_gridA);
  cudaGetSymbolAddress((void**)&gB,   g_gridB);
  cudaGetSymbolAddress((void**)&m0,   g_m0);
  cudaGetSymbolAddress((void**)&m1,   g_m1);
  cudaGetSymbolAddress((void**)&sub0, g_sub0);
  cudaGetSymbolAddress((void**)&cin,  g_cin);
  cudaGetSymbolAddress((void**)&h1,   g_h1);
  cudaGetSymbolAddress((void**)&xc,   g_xc);

  const int TPB=256;
  // A: adj0 of vis*w
  cudaMemsetAsync(gA, 0, (size_t)BATCH*262144*sizeof(float2), 0);
  k_scatter_vis<<<CDIV(BATCH*MVIS,TPB),TPB>>>(gA, vr, vi, w, idx0);
  fft4_rows<512,true ><<<dim3(512,BATCH),128>>>(gA);
  fft4_cols<512,true ,4><<<dim3(128,BATCH),128>>>(gA);
  // B: dir0 -> m0, sub0
  k_prep_dir<512><<<CDIV(BATCH*262144,TPB),TPB>>>(gA);
  fft4_rows<512,false><<<dim3(512,BATCH),128>>>(gA);
  fft4_cols<512,false,4><<<dim3(128,BATCH),128>>>(gA);
  k_gather_m0<<<CDIV(BATCH*MVIS,TPB),TPB>>>(gA, idx0, w, m0, sub0);
  // C: adj1 of m0[sel1]
  cudaMemsetAsync(gB, 0, (size_t)BATCH*65536*sizeof(float2), 0);
  k_scatter_sel<<<CDIV(BATCH*n1,TPB),TPB>>>(gB, m0, sel1, idx1, n1, MVIS, 65536);
  fft4_rows<256,true ><<<dim3(256,BATCH),64>>>(gB);
  fft4_cols<256,true ,8><<<dim3(32,BATCH),64>>>(gB);
  // D: dir1 -> m1
  k_prep_dir<256><<<CDIV(BATCH*65536,TPB),TPB>>>(gB);
  fft4_rows<256,false><<<dim3(256,BATCH),64>>>(gB);
  fft4_cols<256,false,8><<<dim3(32,BATCH),64>>>(gB);
  k_gather<<<CDIV(BATCH*n1,TPB),TPB>>>(gB, idx1, m1, n1, n1, 65536);
  // E: adj2 of m1[sel2]
  cudaMemsetAsync(gA, 0, (size_t)BATCH*16384*sizeof(float2), 0);
  k_scatter_sel<<<CDIV(BATCH*n2,TPB),TPB>>>(gA, m1, sel2, idx2, n2, n1, 16384);
  fft4_rows<128,true ><<<dim3(128,BATCH),32>>>(gA);
  fft4_cols<128,true ,8><<<dim3(16,BATCH),32>>>(gA);
  // F: dir2 -> meas; m1 becomes full1
  k_prep_dir<128><<<CDIV(BATCH*16384,TPB),TPB>>>(gA);
  fft4_rows<128,false><<<dim3(128,BATCH),32>>>(gA);
  fft4_cols<128,false,8><<<dim3(16,BATCH),32>>>(gA);
  k_set_sel<<<CDIV(BATCH*n2,TPB),TPB>>>(m1, sel2, gA, idx2, n2, n1, 16384);
  // G: two adj1 (full1, full1 - sub1)
  cudaMemsetAsync(gA, 0, (size_t)BATCH*65536*sizeof(float2), 0);
  cudaMemsetAsync(gB, 0, (size_t)BATCH*65536*sizeof(float2), 0);
  k_scatterE<<<CDIV(BATCH*n1,TPB),TPB>>>(gA, gB, m1, sub0, sel1, idx1, n1);
  fft4_rows<256,true ><<<dim3(256,BATCH),64>>>(gA);
  fft4_cols<256,true ,8><<<dim3(32,BATCH),64>>>(gA);
  fft4_rows<256,true ><<<dim3(256,BATCH),64>>>(gB);
  fft4_cols<256,true ,8><<<dim3(32,BATCH),64>>>(gB);
  k_extract<256,128><<<CDIV(BATCH*16384,TPB),TPB>>>(gA, gB, cin);
  // H: conv block p0 (F=32 @128) -> xc
  conv1_k <32,128><<<dim3(8,8,BATCH),dim3(16,16)>>>(cin, c0w1, c0b1, c0g1, c0be1, h1);
  conv23_k<32,128><<<dim3(8,8,BATCH),dim3(16,16)>>>(h1, c0w2, c0b2, c0g2, c0be2, c0w3, c0b3, xc);
  // I: dir1 of xc; m0 becomes full0
  k_prep_xc<<<CDIV(BATCH*65536,TPB),TPB>>>(gA, xc);
  fft4_rows<256,false><<<dim3(256,BATCH),64>>>(gA);
  fft4_cols<256,false,8><<<dim3(32,BATCH),64>>>(gA);
  k_set_sel<<<CDIV(BATCH*n1,TPB),TPB>>>(m0, sel1, gA, idx1, n1, MVIS, 65536);
  // J: two adj0 (full0, full0 - sub0)
  cudaMemsetAsync(gA, 0, (size_t)BATCH*262144*sizeof(float2), 0);
  cudaMemsetAsync(gB, 0, (size_t)BATCH*262144*sizeof(float2), 0);
  k_scatterG<<<CDIV(BATCH*MVIS,TPB),TPB>>>(gA, gB, m0, sub0, idx0);
  fft4_rows<512,true ><<<dim3(512,BATCH),128>>>(gA);
  fft4_cols<512,true ,4><<<dim3(128,BATCH),128>>>(gA);
  fft4_rows<512,true ><<<dim3(512,BATCH),128>>>(gB);
  fft4_cols<512,true ,4><<<dim3(128,BATCH),128>>>(gB);
  k_extract<512,256><<<CDIV(BATCH*65536,TPB),TPB>>>(gA, gB, cin);
  // K: conv block p1 (F=16 @256) -> out
  conv1_k <16,256><<<dim3(16,16,BATCH),dim3(16,16)>>>(cin, c1w1, c1b1, c1g1, c1be1, h1);
  conv23_k<16,256><<<dim3(16,16,BATCH),dim3(16,16)>>>(h1, c1w2, c1b2, c1g2, c1be2, c1w3, c1b3, out);
}

// round 6
// speedup vs baseline: 1.2956x; 1.1018x over previous
#include <cuda_runtime.h>
#include <math.h>

#define BATCH 20
#define MVIS 262144
#define CDIV(a,b) (((a)+(b)-1)/(b))
#define RBN 0.99950037f   // 1/sqrt(1.001)

// ---------------- static device scratch ----------------
static __device__ float2 g_gridA[BATCH*512*512];
static __device__ float2 g_gridB[BATCH*512*512];
static __device__ float2 g_m0  [BATCH*MVIS];
static __device__ float2 g_m1  [BATCH*MVIS];
static __device__ float2 g_sub0[BATCH*MVIS];
static __device__ float  g_cin [BATCH*2*256*256];
static __device__ float  g_h1  [BATCH*16*256*256];
static __device__ float  g_xc  [BATCH*128*128];

__device__ __forceinline__ float2 cmulf(float2 a, float2 b){
  return make_float2(fmaf(a.x,b.x,-a.y*b.y), fmaf(a.x,b.y,a.y*b.x));
}
__device__ __forceinline__ constexpr int IX(int i){ return i + (i>>4); }

// ---- packed f32x2 helpers ----
__device__ __forceinline__ unsigned long long pack2(float lo, float hi){
  unsigned long long r;
  asm("mov.b64 %0, {%1, %2};" : "=l"(r) : "r"(__float_as_uint(lo)), "r"(__float_as_uint(hi)));
  return r;
}
__device__ __forceinline__ unsigned long long dup2(float v){
  unsigned long long r;
  asm("mov.b64 %0, {%1, %1};" : "=l"(r) : "r"(__float_as_uint(v)));
  return r;
}
__device__ __forceinline__ void fma2(unsigned long long &d, unsigned long long a,
                                     unsigned long long b, unsigned long long c){
  asm("fma.rn.f32x2 %0, %1, %2, %3;" : "=l"(d) : "l"(a), "l"(b), "l"(c));
}
__device__ __forceinline__ float2 unpack2(unsigned long long v){
  unsigned lo, hi;
  asm("mov.b64 {%0, %1}, %2;" : "=r"(lo), "=r"(hi) : "l"(v));
  return make_float2(__uint_as_float(lo), __uint_as_float(hi));
}

// ---------------- FFT: Stockham radix-4 (+radix-2 tail) ----------------
// Generic radix-4 stage body (s >= 1 usable; also s=0 general).
template<bool INV>
__device__ __forceinline__ void r4_stage(float2* src, float2* dst, int t, int Ns, int N){
  const int jm = t & (Ns-1);
  float sn,cs; sincospif(((INV?2.0f:-2.0f)*jm)/(4*Ns), &sn, &cs);
  float2 w1=make_float2(cs,sn);
  float2 w2=cmulf(w1,w1), w3=cmulf(w2,w1);
  float2 v0=src[IX(t)],       v1=src[IX(t+N/4)];
  float2 v2=src[IX(t+N/2)],   v3=src[IX(t+3*(N/4))];
  float2 a1=cmulf(v1,w1), a2=cmulf(v2,w2), a3=cmulf(v3,w3);
  float2 t0=make_float2(v0.x+a2.x, v0.y+a2.y);
  float2 t1=make_float2(v0.x-a2.x, v0.y-a2.y);
  float2 t2=make_float2(a1.x+a3.x, a1.y+a3.y);
  float2 t3=make_float2(a1.x-a3.x, a1.y-a3.y);
  float2 j3 = INV ? make_float2(-t3.y, t3.x) : make_float2(t3.y, -t3.x);
  int d = ((t - jm) << 2) + jm;
  dst[IX(d)]      = make_float2(t0.x+t2.x, t0.y+t2.y);
  dst[IX(d+Ns)]   = make_float2(t1.x+j3.x, t1.y+j3.y);
  dst[IX(d+2*Ns)] = make_float2(t0.x-t2.x, t0.y-t2.y);
  dst[IX(d+3*Ns)] = make_float2(t1.x-j3.x, t1.y-j3.y);
}
template<bool INV>
__device__ __forceinline__ void r2_tail(float2* src, float2* dst, int t, int N){
  #pragma unroll
  for (int q=0;q<2;q++){
    int j = t + q*(N/4);
    float sn,cs; sincospif(((INV?2.0f:-2.0f)*j)/N, &sn, &cs);
    float2 v0 = src[IX(j)], v1 = src[IX(j+N/2)];
    float2 vw = cmulf(v1, make_float2(cs,sn));
    dst[IX(j)]     = make_float2(v0.x+vw.x, v0.y+vw.y);
    dst[IX(j+N/2)] = make_float2(v0.x-vw.x, v0.y-vw.y);
  }
}

// Full row FFT (used for all adjoint row passes, INV=true)
template<int N, bool INV>
__global__ void fft4_rows(float2* __restrict__ g){
  constexpr int L  = (N==512)?9:(N==256)?8:7;
  constexpr int S4 = L/2;
  constexpr bool ODD = (L & 1);
  __shared__ float2 sh[2][N + N/16];
  const int t = threadIdx.x;                    // N/4 threads
  float2* base = g + ((size_t)blockIdx.y * N + blockIdx.x) * N;
  #pragma unroll
  for (int k=0;k<4;k++) sh[0][IX(t + k*(N/4))] = base[t + k*(N/4)];
  __syncthreads();
  int sb=0;
  #pragma unroll
  for (int s=0; s<S4; s++){
    r4_stage<INV>(sh[sb], sh[sb^1], t, 1<<(2*s), N);
    sb^=1; __syncthreads();
  }
  if (ODD){ r2_tail<INV>(sh[sb], sh[sb^1], t, N); sb^=1; __syncthreads(); }
  const float sc = INV ? 1.0f/N : 1.0f;
  #pragma unroll
  for (int k=0;k<4;k++){
    float2 v = sh[sb][IX(t + k*(N/4))];
    base[t + k*(N/4)] = make_float2(v.x*sc, v.y*sc);
  }
}

// DIR row pass: only rows < N/2 (gridDim.x = N/2); input cols >= N/2 are zero,
// cols < N/2 are taken as Re-only. Simplified twiddle-free stage 0. In-place.
template<int N>
__global__ void fft4_rows_dir(float2* __restrict__ g){
  constexpr int L  = (N==512)?9:(N==256)?8:7;
  constexpr int S4 = L/2;
  constexpr bool ODD = (L & 1);
  __shared__ float2 sh[2][N + N/16];
  const int t = threadIdx.x;                    // N/4 threads
  float2* base = g + ((size_t)blockIdx.y * N + blockIdx.x) * N;
  // stage 0 from global: v0=(x0,0), v1=(x1,0), v2=v3=0, w=1 (forward)
  {
    float x0 = base[t].x, x1 = base[t + N/4].x;
    int d = 4*t;
    sh[0][IX(d)]   = make_float2(x0+x1, 0.f);
    sh[0][IX(d+1)] = make_float2(x0, -x1);
    sh[0][IX(d+2)] = make_float2(x0-x1, 0.f);
    sh[0][IX(d+3)] = make_float2(x0,  x1);
  }
  __syncthreads();
  int sb=0;
  #pragma unroll
  for (int s=1; s<S4; s++){
    r4_stage<false>(sh[sb], sh[sb^1], t, 1<<(2*s), N);
    sb^=1; __syncthreads();
  }
  if (ODD){ r2_tail<false>(sh[sb], sh[sb^1], t, N); sb^=1; __syncthreads(); }
  #pragma unroll
  for (int k=0;k<4;k++) base[t + k*(N/4)] = sh[sb][IX(t + k*(N/4))];
}

// DIR row pass reading a real HxH array (xc), zero-padded to N. Writes grid rows < N/2.
template<int N>
__global__ void fft4_rows_dir_real(float2* __restrict__ g, const float* __restrict__ xr){
  constexpr int L  = (N==512)?9:(N==256)?8:7;
  constexpr int S4 = L/2;
  constexpr bool ODD = (L & 1);
  __shared__ float2 sh[2][N + N/16];
  const int t = threadIdx.x;                    // N/4 threads
  const int y = blockIdx.x, b = blockIdx.y;
  const float* row = xr + ((size_t)b*(N/2) + y)*(N/2);
  float2* base = g + ((size_t)b * N + y) * N;
  {
    float x0 = row[t], x1 = row[t + N/4];
    int d = 4*t;
    sh[0][IX(d)]   = make_float2(x0+x1, 0.f);
    sh[0][IX(d+1)] = make_float2(x0, -x1);
    sh[0][IX(d+2)] = make_float2(x0-x1, 0.f);
    sh[0][IX(d+3)] = make_float2(x0,  x1);
  }
  __syncthreads();
  int sb=0;
  #pragma unroll
  for (int s=1; s<S4; s++){
    r4_stage<false>(sh[sb], sh[sb^1], t, 1<<(2*s), N);
    sb^=1; __syncthreads();
  }
  if (ODD){ r2_tail<false>(sh[sb], sh[sb^1], t, N); sb^=1; __syncthreads(); }
  #pragma unroll
  for (int k=0;k<4;k++) base[t + k*(N/4)] = sh[sb][IX(t + k*(N/4))];
}

// ADJ col pass (inverse), pruned: gridDim.x covers only cols < N/2; stores rows < N/2 only.
template<int N, int TC>
__global__ void fft4_cols_adj(float2* __restrict__ g){
  constexpr int L  = (N==512)?9:(N==256)?8:7;
  constexpr int S4 = L/2;
  constexpr bool ODD = (L & 1);
  __shared__ float2 sh[2][TC][N + N/16];
  const int t = threadIdx.x;                    // N/4 threads
  float2* base = g + (size_t)blockIdx.y * N * N + blockIdx.x * TC;
  for (int i=t; i<N*TC; i+=N/4){
    int r=i/TC, cc=i&(TC-1);
    sh[0][cc][IX(r)] = base[(size_t)r*N + cc];
  }
  __syncthreads();
  int sb=0;
  #pragma unroll
  for (int s=0; s<S4; s++){
    const int Ns = 1 << (2*s);
    const int jm = t & (Ns-1);
    float sn,cs; sincospif((2.0f*jm)/(4*Ns), &sn, &cs);
    float2 w1=make_float2(cs,sn);
    float2 w2=cmulf(w1,w1), w3=cmulf(w2,w1);
    const int d = ((t - jm) << 2) + jm;
    #pragma unroll
    for (int cc=0; cc<TC; cc++){
      float2 v0=sh[sb][cc][IX(t)],     v1=sh[sb][cc][IX(t+N/4)];
      float2 v2=sh[sb][cc][IX(t+N/2)], v3=sh[sb][cc][IX(t+3*(N/4))];
      float2 a1=cmulf(v1,w1), a2=cmulf(v2,w2), a3=cmulf(v3,w3);
      float2 t0=make_float2(v0.x+a2.x, v0.y+a2.y);
      float2 t1=make_float2(v0.x-a2.x, v0.y-a2.y);
      float2 t2=make_float2(a1.x+a3.x, a1.y+a3.y);
      float2 t3=make_float2(a1.x-a3.x, a1.y-a3.y);
      float2 j3 = make_float2(-t3.y, t3.x);
      sh[sb^1][cc][IX(d)]      = make_float2(t0.x+t2.x, t0.y+t2.y);
      sh[sb^1][cc][IX(d+Ns)]   = make_float2(t1.x+j3.x, t1.y+j3.y);
      sh[sb^1][cc][IX(d+2*Ns)] = make_float2(t0.x-t2.x, t0.y-t2.y);
      sh[sb^1][cc][IX(d+3*Ns)] = make_float2(t1.x-j3.x, t1.y-j3.y);
    }
    sb^=1; __syncthreads();
  }
  if (ODD){
    #pragma unroll
    for (int q=0;q<2;q++){
      int j = t + q*(N/4);
      float sn,cs; sincospif((2.0f*j)/N, &sn, &cs);
      float2 w = make_float2(cs,sn);
      #pragma unroll
      for (int cc=0; cc<TC; cc++){
        float2 v0 = sh[sb][cc][IX(j)], v1 = sh[sb][cc][IX(j+N/2)];
        float2 vw = cmulf(v1, w);
        sh[sb^1][cc][IX(j)]     = make_float2(v0.x+vw.x, v0.y+vw.y);
        sh[sb^1][cc][IX(j+N/2)] = make_float2(v0.x-vw.x, v0.y-vw.y);
      }
    }
    sb^=1; __syncthreads();
  }
  const float sc = 1.0f/N;
  for (int i=t; i<(N/2)*TC; i+=N/4){          // store only rows < N/2
    int r=i/TC, cc=i&(TC-1);
    float2 v = sh[sb][cc][IX(r)];
    base[(size_t)r*N + cc] = make_float2(v.x*sc, v.y*sc);
  }
}

// DIR col pass (forward): loads only rows < N/2 (rest implicitly zero), full store.
template<int N, int TC>
__global__ void fft4_cols_dir(float2* __restrict__ g){
  constexpr int L  = (N==512)?9:(N==256)?8:7;
  constexpr int S4 = L/2;
  constexpr bool ODD = (L & 1);
  __shared__ float2 sh[2][TC][N + N/16];
  const int t = threadIdx.x;                    // N/4 threads
  float2* base = g + (size_t)blockIdx.y * N * N + blockIdx.x * TC;
  for (int i=t; i<(N/2)*TC; i+=N/4){            // load only rows < N/2
    int r=i/TC, cc=i&(TC-1);
    sh[0][cc][IX(r)] = base[(size_t)r*N + cc];
  }
  __syncthreads();
  // stage 0: v2=v3=0, w=1
  {
    const int d = 4*t;
    #pragma unroll
    for (int cc=0; cc<TC; cc++){
      float2 v0=sh[0][cc][IX(t)], v1=sh[0][cc][IX(t+N/4)];
      sh[1][cc][IX(d)]   = make_float2(v0.x+v1.x, v0.y+v1.y);
      sh[1][cc][IX(d+1)] = make_float2(v0.x+v1.y, v0.y-v1.x);
      sh[1][cc][IX(d+2)] = make_float2(v0.x-v1.x, v0.y-v1.y);
      sh[1][cc][IX(d+3)] = make_float2(v0.x-v1.y, v0.y+v1.x);
    }
  }
  __syncthreads();
  int sb=1;
  #pragma unroll
  for (int s=1; s<S4; s++){
    const int Ns = 1 << (2*s);
    const int jm = t & (Ns-1);
    float sn,cs; sincospif((-2.0f*jm)/(4*Ns), &sn, &cs);
    float2 w1=make_float2(cs,sn);
    float2 w2=cmulf(w1,w1), w3=cmulf(w2,w1);
    const int d = ((t - jm) << 2) + jm;
    #pragma unroll
    for (int cc=0; cc<TC; cc++){
      float2 v0=sh[sb][cc][IX(t)],     v1=sh[sb][cc][IX(t+N/4)];
      float2 v2=sh[sb][cc][IX(t+N/2)], v3=sh[sb][cc][IX(t+3*(N/4))];
      float2 a1=cmulf(v1,w1), a2=cmulf(v2,w2), a3=cmulf(v3,w3);
      float2 t0=make_float2(v0.x+a2.x, v0.y+a2.y);
      float2 t1=make_float2(v0.x-a2.x, v0.y-a2.y);
      float2 t2=make_float2(a1.x+a3.x, a1.y+a3.y);
      float2 t3=make_float2(a1.x-a3.x, a1.y-a3.y);
      float2 j3 = make_float2(t3.y, -t3.x);
      sh[sb^1][cc][IX(d)]      = make_float2(t0.x+t2.x, t0.y+t2.y);
      sh[sb^1][cc][IX(d+Ns)]   = make_float2(t1.x+j3.x, t1.y+j3.y);
      sh[sb^1][cc][IX(d+2*Ns)] = make_float2(t0.x-t2.x, t0.y-t2.y);
      sh[sb^1][cc][IX(d+3*Ns)] = make_float2(t1.x-j3.x, t1.y-j3.y);
    }
    sb^=1; __syncthreads();
  }
  if (ODD){
    #pragma unroll
    for (int q=0;q<2;q++){
      int j = t + q*(N/4);
      float sn,cs; sincospif((-2.0f*j)/N, &sn, &cs);
      float2 w = make_float2(cs,sn);
      #pragma unroll
      for (int cc=0; cc<TC; cc++){
        float2 v0 = sh[sb][cc][IX(j)], v1 = sh[sb][cc][IX(j+N/2)];
        float2 vw = cmulf(v1, w);
        sh[sb^1][cc][IX(j)]     = make_float2(v0.x+vw.x, v0.y+vw.y);
        sh[sb^1][cc][IX(j+N/2)] = make_float2(v0.x-vw.x, v0.y-vw.y);
      }
    }
    sb^=1; __syncthreads();
  }
  for (int i=t; i<N*TC; i+=N/4){
    int r=i/TC, cc=i&(TC-1);
    base[(size_t)r*N + cc] = sh[sb][cc][IX(r)];
  }
}

// ---------------- NUFFT pieces ----------------
__global__ void k_scatter_vis(float2* __restrict__ grid, const float* __restrict__ vr,
                              const float* __restrict__ vi, const float* __restrict__ w,
                              const int* __restrict__ idx){
  int i = blockIdx.x*blockDim.x+threadIdx.x;
  if (i >= BATCH*MVIS) return;
  int b=i/MVIS, k=i-b*MVIS;
  float wv=w[k]; int gi=b*512*512+idx[k];
  atomicAdd(&grid[gi].x, vr[i]*wv);
  atomicAdd(&grid[gi].y, vi[i]*wv);
}

__global__ void k_gather_m0(const float2* __restrict__ grid, const int* __restrict__ idx,
                            const float* __restrict__ w, float2* __restrict__ m0,
                            float2* __restrict__ sub0){
  int i = blockIdx.x*blockDim.x+threadIdx.x;
  if (i >= BATCH*MVIS) return;
  int b=i/MVIS, k=i-b*MVIS;
  float2 v = grid[b*512*512+idx[k]];
  m0[i]=v; float wv=w[k];
  sub0[i]=make_float2(v.x*wv, v.y*wv);
}

__global__ void k_scatter_sel(float2* __restrict__ grid, const float2* __restrict__ src,
                              const int* __restrict__ sel, const int* __restrict__ idx,
                              int n, int srcStride, int gridSize){
  int i = blockIdx.x*blockDim.x+threadIdx.x;
  if (i >= BATCH*n) return;
  int b=i/n, j=i-b*n;
  float2 v = src[(size_t)b*srcStride + sel[j]];
  int gi = b*gridSize + idx[j];
  atomicAdd(&grid[gi].x, v.x);
  atomicAdd(&grid[gi].y, v.y);
}

__global__ void k_gather(const float2* __restrict__ grid, const int* __restrict__ idx,
                         float2* __restrict__ dst, int n, int dstStride, int gridSize){
  int i = blockIdx.x*blockDim.x+threadIdx.x;
  if (i >= BATCH*n) return;
  int b=i/n, j=i-b*n;
  dst[(size_t)b*dstStride + j] = grid[b*gridSize + idx[j]];
}

__global__ void k_set_sel(float2* __restrict__ dstVec, const int* __restrict__ sel,
                          const float2* __restrict__ grid, const int* __restrict__ idx,
                          int n, int dstStride, int gridSize){
  int i = blockIdx.x*blockDim.x+threadIdx.x;
  if (i >= BATCH*n) return;
  int b=i/n, j=i-b*n;
  dstVec[(size_t)b*dstStride + sel[j]] = grid[b*gridSize + idx[j]];
}

__global__ void k_scatterE(float2* __restrict__ gA, float2* __restrict__ gB,
                           const float2* __restrict__ m1, const float2* __restrict__ sub0,
                           const int* __restrict__ sel1, const int* __restrict__ idx1, int n1){
  int i = blockIdx.x*blockDim.x+threadIdx.x;
  if (i >= BATCH*n1) return;
  int b=i/n1, j=i-b*n1;
  float2 v = m1[(size_t)b*n1 + j];
  float2 s = sub0[(size_t)b*MVIS + sel1[j]];
  int gi = b*65536 + idx1[j];
  atomicAdd(&gA[gi].x, v.x);       atomicAdd(&gA[gi].y, v.y);
  atomicAdd(&gB[gi].x, v.x-s.x);   atomicAdd(&gB[gi].y, v.y-s.y);
}

__global__ void k_scatterG(float2* __restrict__ gA, float2* __restrict__ gB,
                           const float2* __restrict__ m0, const float2* __restrict__ sub0,
                           const int* __restrict__ idx0){
  int i = blockIdx.x*blockDim.x+threadIdx.x;
  if (i >= BATCH*MVIS) return;
  int b=i/MVIS, k=i-b*MVIS;
  float2 v=m0[i], s=sub0[i];
  int gi = b*262144 + idx0[k];
  atomicAdd(&gA[gi].x, v.x);       atomicAdd(&gA[gi].y, v.y);
  atomicAdd(&gB[gi].x, v.x-s.x);   atomicAdd(&gB[gi].y, v.y-s.y);
}

template<int S, int NO>
__global__ void k_extract(const float2* __restrict__ gA, const float2* __restrict__ gB,
                          float* __restrict__ cin){
  int i = blockIdx.x*blockDim.x+threadIdx.x;
  if (i >= BATCH*NO*NO) return;
  int b=i/(NO*NO), p=i-b*NO*NO;
  int y=p/NO, x=p-y*NO;
  size_t gi = (size_t)b*S*S + (size_t)y*S + x;
  cin[(size_t)(b*2+0)*NO*NO + p] = gA[gi].x;
  cin[(size_t)(b*2+1)*NO*NO + p] = gB[gi].x;
}

// ---------------- conv block (packed f32x2) ----------------
template<int F, int H>
__global__ void __launch_bounds__(256) conv1_k(
    const float* __restrict__ cin, const float* __restrict__ W1,
    const float* __restrict__ b1, const float* __restrict__ g1,
    const float* __restrict__ be1, float* __restrict__ h1){
  __shared__ float si[2][18][18];
  __shared__ float sw[18*F];
  __shared__ float sb[F], sg[F], sbe[F];
  const int tx=threadIdx.x, ty=threadIdx.y, tid=ty*16+tx;
  const int b=blockIdx.z, x0=blockIdx.x*16, y0=blockIdx.y*16;
  for (int i=tid; i<18*F; i+=256) sw[i]=W1[i];
  for (int i=tid; i<F; i+=256){ sb[i]=b1[i]; sg[i]=g1[i]*RBN; sbe[i]=be1[i]; }
  const float* cb = cin + (size_t)b*2*H*H;
  for (int c=0;c<2;c++)
    for (int i=tid;i<18*18;i+=256){
      int yy=i/18, xx=i-yy*18;
      int gy=y0+yy-1, gx=x0+xx-1;
      si[c][yy][xx] = (gy>=0&&gy<H&&gx>=0&&gx<H) ? cb[c*H*H + gy*H + gx] : 0.f;
    }
  __syncthreads();
  unsigned long long acc2[F/2];
  #pragma unroll
  for (int o2=0;o2<F/2;o2++) acc2[o2]=pack2(sb[2*o2], sb[2*o2+1]);
  #pragma unroll
  for (int ky=0;ky<3;ky++)
    #pragma unroll
    for (int kx=0;kx<3;kx++)
      #pragma unroll
      for (int c=0;c<2;c++){
        unsigned long long vv = dup2(si[c][ty+ky][tx+kx]);
        const float* wt = sw + ((ky*3+kx)*2+c)*F;
        #pragma unroll
        for (int o2=0;o2<F/2;o2++)
          fma2(acc2[o2], vv, *reinterpret_cast<const unsigned long long*>(wt + 2*o2), acc2[o2]);
      }
  const int y=y0+ty, x=x0+tx;
  float* hb = h1 + (size_t)b*F*H*H + (size_t)y*H + x;
  #pragma unroll
  for (int o2=0;o2<F/2;o2++){
    float2 a = unpack2(acc2[o2]);
    hb[(size_t)(2*o2  )*H*H] = fmaf(fmaxf(a.x,0.f), sg[2*o2  ], sbe[2*o2  ]);
    hb[(size_t)(2*o2+1)*H*H] = fmaf(fmaxf(a.y,0.f), sg[2*o2+1], sbe[2*o2+1]);
  }
}

// conv2 (3x3 F->F, relu, bn) fused with conv3 (1x1 F->1) + sigmoid
template<int F, int H>
__global__ void __launch_bounds__(256) conv23_k(
    const float* __restrict__ h1, const float* __restrict__ W2,
    const float* __restrict__ b2, const float* __restrict__ g2,
    const float* __restrict__ be2, const float* __restrict__ W3,
    const float* __restrict__ b3, float* __restrict__ out){
  __shared__ float sw[9*F*F];
  __shared__ float tile[18][18];
  __shared__ float sb[F], sg[F], sbe[F], sw3[F];
  const int tx=threadIdx.x, ty=threadIdx.y, tid=ty*16+tx;
  const int b=blockIdx.z, x0=blockIdx.x*16, y0=blockIdx.y*16;
  for (int i=tid; i<9*F*F; i+=256){
    int oc=i%F, r=i/F, tap=r%9, ic=r/9;
    sw[i] = W2[(tap*F+ic)*F+oc];
  }
  for (int i=tid; i<F; i+=256){ sb[i]=b2[i]; sg[i]=g2[i]*RBN; sbe[i]=be2[i]; sw3[i]=W3[i]; }
  __syncthreads();
  unsigned long long acc2[F/2];
  #pragma unroll
  for (int o2=0;o2<F/2;o2++) acc2[o2]=pack2(sb[2*o2], sb[2*o2+1]);
  const float* hb = h1 + (size_t)b*F*H*H;
  for (int ic=0; ic<F; ic++){
    __syncthreads();
    for (int i=tid;i<18*18;i+=256){
      int yy=i/18, xx=i-yy*18;
      int gy=y0+yy-1, gx=x0+xx-1;
      tile[yy][xx] = (gy>=0&&gy<H&&gx>=0&&gx<H) ? hb[(size_t)ic*H*H + gy*H + gx] : 0.f;
    }
    __syncthreads();
    const float* wi = sw + ic*9*F;
    #pragma unroll
    for (int ky=0;ky<3;ky++)
      #pragma unroll
      for (int kx=0;kx<3;kx++){
        unsigned long long vv = dup2(tile[ty+ky][tx+kx]);
        const float* wt = wi + (ky*3+kx)*F;
        #pragma unroll
        for (int o2=0;o2<F/2;o2++)
          fma2(acc2[o2], vv, *reinterpret_cast<const unsigned long long*>(wt + 2*o2), acc2[o2]);
      }
  }
  float s = b3[0];
  #pragma unroll
  for (int o2=0;o2<F/2;o2++){
    float2 a = unpack2(acc2[o2]);
    s = fmaf(fmaf(fmaxf(a.x,0.f), sg[2*o2  ], sbe[2*o2  ]), sw3[2*o2  ], s);
    s = fmaf(fmaf(fmaxf(a.y,0.f), sg[2*o2+1], sbe[2*o2+1]), sw3[2*o2+1], s);
  }
  out[(size_t)b*H*H + (size_t)(y0+ty)*H + (x0+tx)] = 1.f/(1.f+__expf(-s));
}

// ---------------- launch ----------------
extern "C" void kernel_launch(void* const* d_in, const int* in_sizes, int n_in,
                              void* d_out, int out_size){
  const float* vr = (const float*)d_in[0];
  const float* vi = (const float*)d_in[1];
  const float* w  = (const float*)d_in[2];
  const float *c0w1=(const float*)d_in[3],  *c0b1=(const float*)d_in[4],
              *c0g1=(const float*)d_in[5],  *c0be1=(const float*)d_in[6],
              *c0w2=(const float*)d_in[7],  *c0b2=(const float*)d_in[8],
              *c0g2=(const float*)d_in[9],  *c0be2=(const float*)d_in[10],
              *c0w3=(const float*)d_in[11], *c0b3=(const float*)d_in[12];
  const float *c1w1=(const float*)d_in[13], *c1b1=(const float*)d_in[14],
              *c1g1=(const float*)d_in[15], *c1be1=(const float*)d_in[16],
              *c1w2=(const float*)d_in[17], *c1b2=(const float*)d_in[18],
              *c1g2=(const float*)d_in[19], *c1be2=(const float*)d_in[20],
              *c1w3=(const float*)d_in[21], *c1b3=(const float*)d_in[22];
  const int* idx0=(const int*)d_in[23];
  const int* idx1=(const int*)d_in[24];
  const int* idx2=(const int*)d_in[25];
  const int* sel1=(const int*)d_in[26];
  const int* sel2=(const int*)d_in[27];
  const int n1 = in_sizes[24], n2 = in_sizes[25];
  float* out = (float*)d_out;

  float2 *gA,*gB,*m0,*m1,*sub0; float *cin,*h1,*xc;
  cudaGetSymbolAddress((void**)&gA,   g_gridA);
  cudaGetSymbolAddress((void**)&gB,   g_gridB);
  cudaGetSymbolAddress((void**)&m0,   g_m0);
  cudaGetSymbolAddress((void**)&m1,   g_m1);
  cudaGetSymbolAddress((void**)&sub0, g_sub0);
  cudaGetSymbolAddress((void**)&cin,  g_cin);
  cudaGetSymbolAddress((void**)&h1,   g_h1);
  cudaGetSymbolAddress((void**)&xc,   g_xc);

  const int TPB=256;
  // A: adj0 of vis*w (col pass pruned to quadrant output)
  cudaMemsetAsync(gA, 0, (size_t)BATCH*262144*sizeof(float2), 0);
  k_scatter_vis<<<CDIV(BATCH*MVIS,TPB),TPB>>>(gA, vr, vi, w, idx0);
  fft4_rows<512,true ><<<dim3(512,BATCH),128>>>(gA);
  fft4_cols_adj<512,4><<<dim3(64,BATCH),128>>>(gA);
  // B: dir0 (fused Re-quadrant prep) -> m0, sub0
  fft4_rows_dir<512><<<dim3(256,BATCH),128>>>(gA);
  fft4_cols_dir<512,4><<<dim3(128,BATCH),128>>>(gA);
  k_gather_m0<<<CDIV(BATCH*MVIS,TPB),TPB>>>(gA, idx0, w, m0, sub0);
  // C: adj1 of m0[sel1]
  cudaMemsetAsync(gB, 0, (size_t)BATCH*65536*sizeof(float2), 0);
  k_scatter_sel<<<CDIV(BATCH*n1,TPB),TPB>>>(gB, m0, sel1, idx1, n1, MVIS, 65536);
  fft4_rows<256,true ><<<dim3(256,BATCH),64>>>(gB);
  fft4_cols_adj<256,8><<<dim3(16,BATCH),64>>>(gB);
  // D: dir1 -> m1
  fft4_rows_dir<256><<<dim3(128,BATCH),64>>>(gB);
  fft4_cols_dir<256,8><<<dim3(32,BATCH),64>>>(gB);
  k_gather<<<CDIV(BATCH*n1,TPB),TPB>>>(gB, idx1, m1, n1, n1, 65536);
  // E: adj2 of m1[sel2]
  cudaMemsetAsync(gA, 0, (size_t)BATCH*16384*sizeof(float2), 0);
  k_scatter_sel<<<CDIV(BATCH*n2,TPB),TPB>>>(gA, m1, sel2, idx2, n2, n1, 16384);
  fft4_rows<128,true ><<<dim3(128,BATCH),32>>>(gA);
  fft4_cols_adj<128,8><<<dim3(8,BATCH),32>>>(gA);
  // F: dir2 -> meas; m1 becomes full1
  fft4_rows_dir<128><<<dim3(64,BATCH),32>>>(gA);
  fft4_cols_dir<128,8><<<dim3(16,BATCH),32>>>(gA);
  k_set_sel<<<CDIV(BATCH*n2,TPB),TPB>>>(m1, sel2, gA, idx2, n2, n1, 16384);
  // G: two adj1 (full1, full1 - sub1) -> conv input quadrants
  cudaMemsetAsync(gA, 0, (size_t)BATCH*65536*sizeof(float2), 0);
  cudaMemsetAsync(gB, 0, (size_t)BATCH*65536*sizeof(float2), 0);
  k_scatterE<<<CDIV(BATCH*n1,TPB),TPB>>>(gA, gB, m1, sub0, sel1, idx1, n1);
  fft4_rows<256,true ><<<dim3(256,BATCH),64>>>(gA);
  fft4_cols_adj<256,8><<<dim3(16,BATCH),64>>>(gA);
  fft4_rows<256,true ><<<dim3(256,BATCH),64>>>(gB);
  fft4_cols_adj<256,8><<<dim3(16,BATCH),64>>>(gB);
  k_extract<256,128><<<CDIV(BATCH*16384,TPB),TPB>>>(gA, gB, cin);
  // H: conv block p0 (F=32 @128) -> xc
  conv1_k <32,128><<<dim3(8,8,BATCH),dim3(16,16)>>>(cin, c0w1, c0b1, c0g1, c0be1, h1);
  conv23_k<32,128><<<dim3(8,8,BATCH),dim3(16,16)>>>(h1, c0w2, c0b2, c0g2, c0be2, c0w3, c0b3, xc);
  // I: dir1 of xc (reads xc directly, no prep); m0 becomes full0
  fft4_rows_dir_real<256><<<dim3(128,BATCH),64>>>(gA, xc);
  fft4_cols_dir<256,8><<<dim3(32,BATCH),64>>>(gA);
  k_set_sel<<<CDIV(BATCH*n1,TPB),TPB>>>(m0, sel1, gA, idx1, n1, MVIS, 65536);
  // J: two adj0 (full0, full0 - sub0) -> conv input quadrants
  cudaMemsetAsync(gA, 0, (size_t)BATCH*262144*sizeof(float2), 0);
  cudaMemsetAsync(gB, 0, (size_t)BATCH*262144*sizeof(float2), 0);
  k_scatterG<<<CDIV(BATCH*MVIS,TPB),TPB>>>(gA, gB, m0, sub0, idx0);
  fft4_rows<512,true ><<<dim3(512,BATCH),128>>>(gA);
  fft4_cols_adj<512,4><<<dim3(64,BATCH),128>>>(gA);
  fft4_rows<512,true ><<<dim3(512,BATCH),128>>>(gB);
  fft4_cols_adj<512,4><<<dim3(64,BATCH),128>>>(gB);
  k_extract<512,256><<<CDIV(BATCH*65536,TPB),TPB>>>(gA, gB, cin);
  // K: conv block p1 (F=16 @256) -> out
  conv1_k <16,256><<<dim3(16,16,BATCH),dim3(16,16)>>>(cin, c1w1, c1b1, c1g1, c1be1, h1);
  conv23_k<16,256><<<dim3(16,16,BATCH),dim3(16,16)>>>(h1, c1w2, c1b2, c1g2, c1be2, c1w3, c1b3, out);
}